// round 3
// baseline (speedup 1.0000x reference)
#include <cuda_runtime.h>
#include <cstdint>

#define ENC_DIM 1024
#define TOK_DIM 4096
#define NB 8
#define NT 3000
#define M_TOTAL 4096
#define FRATE 50.0f
#define LN_EPS 1e-5f

// ---------------- GEMM tiling (SIMT, fp32, FFMA2) ----------------
#define BM 128
#define BN 128
#define BK 16
#define NKT (ENC_DIM / BK)      // 64 k-tiles

// ---------------- scratch (static device memory — no allocations) ----------------
__device__ float g_pooled[(size_t)M_TOTAL * ENC_DIM];   // 16 MB
__device__ float g_h[(size_t)M_TOTAL * TOK_DIM];        // 64 MB

// ---------------- packed f32x2 helpers (Blackwell FFMA2) ----------------
__device__ __forceinline__ void ffma2(uint64_t& d, uint64_t a, uint64_t b) {
    asm("fma.rn.f32x2 %0, %1, %2, %3;" : "=l"(d) : "l"(a), "l"(b), "l"(d));
}
__device__ __forceinline__ uint64_t pk2(float lo, float hi) {
    uint64_t r;
    asm("mov.b64 %0, {%1, %2};" : "=l"(r) : "f"(lo), "f"(hi));
    return r;
}
__device__ __forceinline__ float2 upk2(uint64_t v) {
    float2 r;
    asm("mov.b64 {%0, %1}, %2;" : "=f"(r.x), "=f"(r.y) : "l"(v));
    return r;
}

// ---------------- kernel 1: ragged mean-pool ----------------
__global__ void __launch_bounds__(256) pool_kernel(const float* __restrict__ x,
                                                   const float* __restrict__ ts) {
    const int tok = blockIdx.x;            // b*512 + n
    const int b   = tok >> 9;
    const int t   = threadIdx.x;           // 0..255 -> one float4 of the 1024-dim
    const float2 tt = ((const float2*)ts)[tok];
    int s = (int)floorf(tt.x * FRATE);
    int e = (int)floorf(tt.y * FRATE);
    if (e < s + 1) e = s + 1;
    if (e > NT) e = NT;
    const float4* xb = (const float4*)(x + (size_t)b * NT * ENC_DIM);
    float4 acc = make_float4(0.f, 0.f, 0.f, 0.f);
    for (int f = s; f < e; f++) {
        float4 v = xb[(size_t)f * (ENC_DIM / 4) + t];
        acc.x += v.x; acc.y += v.y; acc.z += v.z; acc.w += v.w;
    }
    const float inv = 1.f / (float)(e - s);
    float4 o;
    o.x = acc.x * inv; o.y = acc.y * inv; o.z = acc.z * inv; o.w = acc.w * inv;
    ((float4*)g_pooled)[(size_t)tok * (ENC_DIM / 4) + t] = o;
}

// ---------------- kernel 2: SIMT fp32 GEMM + bias + relu -> g_h ----------------
// H[m][n] = relu( sum_k A[m][k] * W[n][k] + bias[n] ),  A = g_pooled
// block = 256 thr, tile 128x128, BK=16, double-buffered via regs+smem.
__global__ void __launch_bounds__(256) sgemm_kernel(const float* __restrict__ W,
                                                    const float* __restrict__ bias) {
    __shared__ float As[2][BK][BM + 4];    // [k][m], transposed at store
    __shared__ float Bs[2][BK][BN + 4];    // [k][n]

    const int tid = threadIdx.x;
    const int bm = blockIdx.y * BM;
    const int bn = blockIdx.x * BN;

    // loader mapping: 2 float4 per operand per thread
    const int r0 = tid >> 2;               // 0..63
    const int c4 = (tid & 3) * 4;          // 0,4,8,12
    const float* Ag = g_pooled + (size_t)(bm + r0) * ENC_DIM + c4;
    const float* Ag2 = Ag + 64 * ENC_DIM;
    const float* Wg = W + (size_t)(bn + r0) * ENC_DIM + c4;
    const float* Wg2 = Wg + 64 * ENC_DIM;

    // compute mapping: warp 4x2, thread 4x8 -> 8m x 8n per thread
    const int wid = tid >> 5, lane = tid & 31;
    const int wm = wid >> 1, wn = wid & 1;
    const int lm = lane >> 3, ln = lane & 7;
    const int m0 = wm * 32 + lm * 8;
    const int n0 = wn * 64 + ln * 8;

    uint64_t acc[8][4];
    #pragma unroll
    for (int i = 0; i < 8; i++)
        #pragma unroll
        for (int j = 0; j < 4; j++) acc[i][j] = 0ull;

    float4 ra0, ra1, rb0, rb1;

    // prologue: tile 0 -> regs -> smem[0]
    ra0 = *(const float4*)(Ag);  ra1 = *(const float4*)(Ag2);
    rb0 = *(const float4*)(Wg);  rb1 = *(const float4*)(Wg2);
    #pragma unroll
    for (int j = 0; j < 4; j++) {
        As[0][c4 + j][r0]      = ((const float*)&ra0)[j];
        As[0][c4 + j][r0 + 64] = ((const float*)&ra1)[j];
        Bs[0][c4 + j][r0]      = ((const float*)&rb0)[j];
        Bs[0][c4 + j][r0 + 64] = ((const float*)&rb1)[j];
    }
    __syncthreads();
    // tile 1 -> regs (in flight during compute of tile 0)
    ra0 = *(const float4*)(Ag + BK);  ra1 = *(const float4*)(Ag2 + BK);
    rb0 = *(const float4*)(Wg + BK);  rb1 = *(const float4*)(Wg2 + BK);

    for (int kt = 0; kt < NKT; kt++) {
        const int buf = kt & 1;
        #pragma unroll
        for (int k = 0; k < BK; k++) {
            float4 a03 = *(const float4*)&As[buf][k][m0];
            float4 a47 = *(const float4*)&As[buf][k][m0 + 4];
            float4 b03 = *(const float4*)&Bs[buf][k][n0];
            float4 b47 = *(const float4*)&Bs[buf][k][n0 + 4];
            uint64_t pb[4];
            pb[0] = pk2(b03.x, b03.y); pb[1] = pk2(b03.z, b03.w);
            pb[2] = pk2(b47.x, b47.y); pb[3] = pk2(b47.z, b47.w);
            uint64_t pa[8];
            pa[0] = pk2(a03.x, a03.x); pa[1] = pk2(a03.y, a03.y);
            pa[2] = pk2(a03.z, a03.z); pa[3] = pk2(a03.w, a03.w);
            pa[4] = pk2(a47.x, a47.x); pa[5] = pk2(a47.y, a47.y);
            pa[6] = pk2(a47.z, a47.z); pa[7] = pk2(a47.w, a47.w);
            #pragma unroll
            for (int i = 0; i < 8; i++)
                #pragma unroll
                for (int j = 0; j < 4; j++) ffma2(acc[i][j], pa[i], pb[j]);
        }
        if (kt < NKT - 1) {
            __syncthreads();                       // all readers of smem[kt+1 & 1] done
            const int nb = (kt + 1) & 1;
            #pragma unroll
            for (int j = 0; j < 4; j++) {
                As[nb][c4 + j][r0]      = ((const float*)&ra0)[j];
                As[nb][c4 + j][r0 + 64] = ((const float*)&ra1)[j];
                Bs[nb][c4 + j][r0]      = ((const float*)&rb0)[j];
                Bs[nb][c4 + j][r0 + 64] = ((const float*)&rb1)[j];
            }
            if (kt + 2 < NKT) {
                const int ko = (kt + 2) * BK;
                ra0 = *(const float4*)(Ag + ko);  ra1 = *(const float4*)(Ag2 + ko);
                rb0 = *(const float4*)(Wg + ko);  rb1 = *(const float4*)(Wg2 + ko);
            }
            __syncthreads();                       // stores visible before next compute
        }
    }

    // epilogue: bias + relu, vectorized stores
    float4 bv0 = *(const float4*)(bias + bn + n0);
    float4 bv1 = *(const float4*)(bias + bn + n0 + 4);
    #pragma unroll
    for (int i = 0; i < 8; i++) {
        float* hrow = g_h + (size_t)(bm + m0 + i) * TOK_DIM + bn + n0;
        float2 u0 = upk2(acc[i][0]), u1 = upk2(acc[i][1]);
        float2 u2 = upk2(acc[i][2]), u3 = upk2(acc[i][3]);
        float4 o0, o1;
        o0.x = fmaxf(u0.x + bv0.x, 0.f); o0.y = fmaxf(u0.y + bv0.y, 0.f);
        o0.z = fmaxf(u1.x + bv0.z, 0.f); o0.w = fmaxf(u1.y + bv0.w, 0.f);
        o1.x = fmaxf(u2.x + bv1.x, 0.f); o1.y = fmaxf(u2.y + bv1.y, 0.f);
        o1.z = fmaxf(u3.x + bv1.z, 0.f); o1.w = fmaxf(u3.y + bv1.w, 0.f);
        *(float4*)(hrow)     = o0;
        *(float4*)(hrow + 4) = o1;
    }
}

// ---------------- kernel 3: LayerNorm over 4096 -> out ----------------
__global__ void __launch_bounds__(256) ln_kernel(const float* __restrict__ gamma,
                                                 const float* __restrict__ beta,
                                                 float* __restrict__ out) {
    const int rowid = blockIdx.x;
    const int t = threadIdx.x;
    const float4* h4 = (const float4*)(g_h + (size_t)rowid * TOK_DIM);
    float4 v[4];
    float sum = 0.f;
    #pragma unroll
    for (int i = 0; i < 4; i++) {
        v[i] = h4[i * 256 + t];
        sum += v[i].x + v[i].y + v[i].z + v[i].w;
    }
    __shared__ float red1[8], red2[8];
    #pragma unroll
    for (int o = 16; o > 0; o >>= 1) sum += __shfl_xor_sync(0xffffffffu, sum, o);
    if ((t & 31) == 0) red1[t >> 5] = sum;
    __syncthreads();
    float tot = 0.f;
    #pragma unroll
    for (int i = 0; i < 8; i++) tot += red1[i];
    const float mu = tot * (1.f / TOK_DIM);

    float sq = 0.f;
    #pragma unroll
    for (int i = 0; i < 4; i++) {
        float dx = v[i].x - mu, dy = v[i].y - mu, dz = v[i].z - mu, dw = v[i].w - mu;
        sq += dx * dx + dy * dy + dz * dz + dw * dw;
    }
    #pragma unroll
    for (int o = 16; o > 0; o >>= 1) sq += __shfl_xor_sync(0xffffffffu, sq, o);
    if ((t & 31) == 0) red2[t >> 5] = sq;
    __syncthreads();
    float tot2 = 0.f;
    #pragma unroll
    for (int i = 0; i < 8; i++) tot2 += red2[i];
    const float rstd = 1.f / sqrtf(tot2 * (1.f / TOK_DIM) + LN_EPS);

    const float4* g4 = (const float4*)gamma;
    const float4* b4 = (const float4*)beta;
    float4* o4 = (float4*)(out + (size_t)rowid * TOK_DIM);
    #pragma unroll
    for (int i = 0; i < 4; i++) {
        const int idx = i * 256 + t;
        const float4 gv = g4[idx], bv = b4[idx];
        float4 r;
        r.x = (v[i].x - mu) * rstd * gv.x + bv.x;
        r.y = (v[i].y - mu) * rstd * gv.y + bv.y;
        r.z = (v[i].z - mu) * rstd * gv.z + bv.z;
        r.w = (v[i].w - mu) * rstd * gv.w + bv.w;
        o4[idx] = r;
    }
}

// ---------------- launcher ----------------
extern "C" void kernel_launch(void* const* d_in, const int* in_sizes, int n_in,
                              void* d_out, int out_size) {
    const float* x     = (const float*)d_in[0];   // [8,3000,1024]
    const float* ts    = (const float*)d_in[1];   // [8,512,2]
    const float* W     = (const float*)d_in[2];   // [4096,1024]
    const float* b     = (const float*)d_in[3];   // [4096]
    const float* gamma = (const float*)d_in[4];   // [4096]
    const float* beta  = (const float*)d_in[5];   // [4096]
    float* out = (float*)d_out;                   // [8,512,4096]

    pool_kernel<<<M_TOTAL, 256>>>(x, ts);
    dim3 gg(TOK_DIM / BN, M_TOTAL / BM);          // 32 x 32
    sgemm_kernel<<<gg, 256>>>(W, b);
    ln_kernel<<<M_TOTAL, 256>>>(gamma, beta, out);
}

// round 6
// speedup vs baseline: 1.2639x; 1.2639x over previous
#include <cuda_runtime.h>
#include <cuda_bf16.h>
#include <cstdint>

#define ENC_DIM 1024
#define TOK_DIM 4096
#define NB 8
#define NT 3000
#define M_TOTAL 4096
#define FRATE 50.0f
#define LN_EPS 1e-5f

// ---------------- HMMA GEMM tiling ----------------
#define BM 128
#define BN 256
#define BK 32                       // bf16 per chunk
#define PADK 40                     // padded row length (bf16) -> 80B rows
#define A_STAGE (BM * PADK * 2)     // 10240 B
#define B_STAGE (BN * PADK * 2)     // 20480 B
#define HG_SMEM (2 * A_STAGE + 2 * B_STAGE)   // 61440 B
#define NCH_TOT (3 * (ENC_DIM / BK))          // 96 chunks (3 plane pairs x 32)

// ---------------- scratch ----------------
__device__ __nv_bfloat16 g_a_hi[(size_t)M_TOTAL * ENC_DIM];
__device__ __nv_bfloat16 g_a_lo[(size_t)M_TOTAL * ENC_DIM];
__device__ __nv_bfloat16 g_b_hi[(size_t)TOK_DIM * ENC_DIM];
__device__ __nv_bfloat16 g_b_lo[(size_t)TOK_DIM * ENC_DIM];
__device__ float g_h[(size_t)M_TOTAL * TOK_DIM];

// ---------------- PTX helpers ----------------
__device__ __forceinline__ uint32_t smem_u32(const void* p) {
    uint32_t r;
    asm("{ .reg .u64 t; cvta.to.shared.u64 t, %1; cvt.u32.u64 %0, t; }" : "=r"(r) : "l"(p));
    return r;
}
__device__ __forceinline__ void cp_async16(uint32_t s, const void* g) {
    asm volatile("cp.async.cg.shared.global [%0], [%1], 16;" :: "r"(s), "l"(g) : "memory");
}
__device__ __forceinline__ void mma16816(float* d, const uint32_t* a, const uint32_t* b) {
    asm volatile(
        "mma.sync.aligned.m16n8k16.row.col.f32.bf16.bf16.f32 "
        "{%0,%1,%2,%3}, {%4,%5,%6,%7}, {%8,%9}, {%0,%1,%2,%3};"
        : "+f"(d[0]), "+f"(d[1]), "+f"(d[2]), "+f"(d[3])
        : "r"(a[0]), "r"(a[1]), "r"(a[2]), "r"(a[3]), "r"(b[0]), "r"(b[1]));
}

__device__ __forceinline__ void split_bf16(float x, __nv_bfloat16& hi, __nv_bfloat16& lo) {
    hi = __float2bfloat16(x);
    lo = __float2bfloat16(x - __bfloat162float(hi));
}

// ---------------- kernel 1: ragged mean-pool -> bf16 hi/lo planes ----------------
__global__ void __launch_bounds__(256) pool_kernel(const float* __restrict__ x,
                                                   const float* __restrict__ ts) {
    const int tok = blockIdx.x;
    const int b   = tok >> 9;
    const int t   = threadIdx.x;
    const float2 tt = ((const float2*)ts)[tok];
    int s = (int)floorf(tt.x * FRATE);
    int e = (int)floorf(tt.y * FRATE);
    if (e < s + 1) e = s + 1;
    if (e > NT) e = NT;
    const float4* xb = (const float4*)(x + (size_t)b * NT * ENC_DIM);
    float4 acc = make_float4(0.f, 0.f, 0.f, 0.f);
    for (int f = s; f < e; f++) {
        float4 v = xb[(size_t)f * (ENC_DIM / 4) + t];
        acc.x += v.x; acc.y += v.y; acc.z += v.z; acc.w += v.w;
    }
    const float inv = 1.f / (float)(e - s);
    float m[4] = {acc.x * inv, acc.y * inv, acc.z * inv, acc.w * inv};
    __nv_bfloat16 hi[4], lo[4];
    #pragma unroll
    for (int i = 0; i < 4; i++) split_bf16(m[i], hi[i], lo[i]);
    const size_t base = (size_t)tok * ENC_DIM + t * 4;
    *(uint2*)(g_a_hi + base) = *(uint2*)hi;
    *(uint2*)(g_a_lo + base) = *(uint2*)lo;
}

// ---------------- kernel 2: W -> bf16 hi/lo planes ----------------
__global__ void __launch_bounds__(256) wsplit_kernel(const float* __restrict__ W) {
    size_t i = ((size_t)blockIdx.x * 256 + threadIdx.x) * 4;
    float4 v = *(const float4*)(W + i);
    __nv_bfloat16 hi[4], lo[4];
    split_bf16(v.x, hi[0], lo[0]); split_bf16(v.y, hi[1], lo[1]);
    split_bf16(v.z, hi[2], lo[2]); split_bf16(v.w, hi[3], lo[3]);
    *(uint2*)(g_b_hi + i) = *(uint2*)hi;
    *(uint2*)(g_b_lo + i) = *(uint2*)lo;
}

// ---------------- kernel 3: mma.sync bf16 split GEMM + bias + relu ----------------
// D[m][n] = sum over 3 plane pairs of A_p[m][k] * B_p[n][k]; warp tile 64x64.
__global__ void __launch_bounds__(256, 1) hgemm_kernel(const float* __restrict__ bias) {
    extern __shared__ __align__(16) char dsm[];
    const int tid  = threadIdx.x;
    const int wid  = tid >> 5;
    const int lane = tid & 31;
    const int g    = lane >> 2;          // group id 0..7
    const int t    = lane & 3;           // thread-in-group 0..3
    const int wm   = wid >> 2;           // 0..1
    const int wn   = wid & 3;            // 0..3
    const int m0 = blockIdx.y * BM;
    const int n0 = blockIdx.x * BN;

    const uint32_t smem0 = smem_u32(dsm);

    const __nv_bfloat16* Apl[3] = {g_a_hi, g_a_hi, g_a_lo};
    const __nv_bfloat16* Bpl[3] = {g_b_hi, g_b_lo, g_b_hi};

    float acc[4][8][4];
    #pragma unroll
    for (int i = 0; i < 4; i++)
        #pragma unroll
        for (int j = 0; j < 8; j++)
            #pragma unroll
            for (int q = 0; q < 4; q++) acc[i][j][q] = 0.f;

    // loader mapping: A -> thread covers row tid>>1, segs (tid&1)*2+{0,1}
    //                 B -> thread covers row tid,    segs 0..3
    const int arow = tid >> 1;
    const int aseg = (tid & 1) * 2;

    auto load_chunk = [&](int c, int buf) {
        const int p  = c >> 5;
        const int ko = (c & 31) * BK;
        const __nv_bfloat16* Ab = Apl[p] + (size_t)(m0 + arow) * ENC_DIM + ko;
        const uint32_t sa = smem0 + buf * A_STAGE + arow * (PADK * 2);
        cp_async16(sa + aseg * 16,       Ab + aseg * 8);
        cp_async16(sa + (aseg + 1) * 16, Ab + (aseg + 1) * 8);
        const __nv_bfloat16* Bb = Bpl[p] + (size_t)(n0 + tid) * ENC_DIM + ko;
        const uint32_t sb = smem0 + 2 * A_STAGE + buf * B_STAGE + tid * (PADK * 2);
        #pragma unroll
        for (int s2 = 0; s2 < 4; s2++) cp_async16(sb + s2 * 16, Bb + s2 * 8);
    };

    load_chunk(0, 0);
    asm volatile("cp.async.commit_group;" ::: "memory");

    int buf = 0;
    for (int c = 0; c < NCH_TOT; c++) {
        if (c + 1 < NCH_TOT) load_chunk(c + 1, buf ^ 1);
        asm volatile("cp.async.commit_group;" ::: "memory");
        asm volatile("cp.async.wait_group 1;" ::: "memory");
        __syncthreads();

        const char* sAb = dsm + buf * A_STAGE;
        const char* sBb = dsm + 2 * A_STAGE + buf * B_STAGE;
        #pragma unroll
        for (int ks = 0; ks < 2; ks++) {
            const int kb = ks * 32 + t * 4;        // byte offset of this thread's k-pair
            uint32_t a[4][4], bfr[8][2];
            #pragma unroll
            for (int i = 0; i < 4; i++) {
                const int r = wm * 64 + i * 16 + g;
                a[i][0] = *(const uint32_t*)(sAb + r * 80 + kb);
                a[i][1] = *(const uint32_t*)(sAb + (r + 8) * 80 + kb);
                a[i][2] = *(const uint32_t*)(sAb + r * 80 + kb + 16);
                a[i][3] = *(const uint32_t*)(sAb + (r + 8) * 80 + kb + 16);
            }
            #pragma unroll
            for (int j = 0; j < 8; j++) {
                const int r = wn * 64 + j * 8 + g;
                bfr[j][0] = *(const uint32_t*)(sBb + r * 80 + kb);
                bfr[j][1] = *(const uint32_t*)(sBb + r * 80 + kb + 16);
            }
            #pragma unroll
            for (int i = 0; i < 4; i++)
                #pragma unroll
                for (int j = 0; j < 8; j++) mma16816(acc[i][j], a[i], bfr[j]);
        }
        __syncthreads();
        buf ^= 1;
    }

    // epilogue: bias + relu -> g_h
    #pragma unroll
    for (int j = 0; j < 8; j++) {
        const int cb = n0 + wn * 64 + j * 8 + t * 2;
        const float2 bv = *(const float2*)(bias + cb);
        #pragma unroll
        for (int i = 0; i < 4; i++) {
            const int r0 = m0 + wm * 64 + i * 16 + g;
            float2 o0, o1;
            o0.x = fmaxf(acc[i][j][0] + bv.x, 0.f);
            o0.y = fmaxf(acc[i][j][1] + bv.y, 0.f);
            o1.x = fmaxf(acc[i][j][2] + bv.x, 0.f);
            o1.y = fmaxf(acc[i][j][3] + bv.y, 0.f);
            *(float2*)(g_h + (size_t)r0 * TOK_DIM + cb)       = o0;
            *(float2*)(g_h + (size_t)(r0 + 8) * TOK_DIM + cb) = o1;
        }
    }
}

// ---------------- kernel 4: LayerNorm over 4096 -> out ----------------
__global__ void __launch_bounds__(256) ln_kernel(const float* __restrict__ gamma,
                                                 const float* __restrict__ beta,
                                                 float* __restrict__ out) {
    const int rowid = blockIdx.x;
    const int t = threadIdx.x;
    const float4* h4 = (const float4*)(g_h + (size_t)rowid * TOK_DIM);
    float4 v[4];
    float sum = 0.f;
    #pragma unroll
    for (int i = 0; i < 4; i++) {
        v[i] = h4[i * 256 + t];
        sum += v[i].x + v[i].y + v[i].z + v[i].w;
    }
    __shared__ float red1[8], red2[8];
    #pragma unroll
    for (int o = 16; o > 0; o >>= 1) sum += __shfl_xor_sync(0xffffffffu, sum, o);
    if ((t & 31) == 0) red1[t >> 5] = sum;
    __syncthreads();
    float tot = 0.f;
    #pragma unroll
    for (int i = 0; i < 8; i++) tot += red1[i];
    const float mu = tot * (1.f / TOK_DIM);

    float sq = 0.f;
    #pragma unroll
    for (int i = 0; i < 4; i++) {
        float dx = v[i].x - mu, dy = v[i].y - mu, dz = v[i].z - mu, dw = v[i].w - mu;
        sq += dx * dx + dy * dy + dz * dz + dw * dw;
    }
    #pragma unroll
    for (int o = 16; o > 0; o >>= 1) sq += __shfl_xor_sync(0xffffffffu, sq, o);
    if ((t & 31) == 0) red2[t >> 5] = sq;
    __syncthreads();
    float tot2 = 0.f;
    #pragma unroll
    for (int i = 0; i < 8; i++) tot2 += red2[i];
    const float rstd = 1.f / sqrtf(tot2 * (1.f / TOK_DIM) + LN_EPS);

    const float4* g4 = (const float4*)gamma;
    const float4* b4 = (const float4*)beta;
    float4* o4 = (float4*)(out + (size_t)rowid * TOK_DIM);
    #pragma unroll
    for (int i = 0; i < 4; i++) {
        const int idx = i * 256 + t;
        const float4 gv = g4[idx], bv = b4[idx];
        float4 r;
        r.x = (v[i].x - mu) * rstd * gv.x + bv.x;
        r.y = (v[i].y - mu) * rstd * gv.y + bv.y;
        r.z = (v[i].z - mu) * rstd * gv.z + bv.z;
        r.w = (v[i].w - mu) * rstd * gv.w + bv.w;
        o4[idx] = r;
    }
}

// ---------------- launcher ----------------
extern "C" void kernel_launch(void* const* d_in, const int* in_sizes, int n_in,
                              void* d_out, int out_size) {
    const float* x     = (const float*)d_in[0];
    const float* ts    = (const float*)d_in[1];
    const float* W     = (const float*)d_in[2];
    const float* b     = (const float*)d_in[3];
    const float* gamma = (const float*)d_in[4];
    const float* beta  = (const float*)d_in[5];
    float* out = (float*)d_out;

    cudaFuncSetAttribute(hgemm_kernel, cudaFuncAttributeMaxDynamicSharedMemorySize, HG_SMEM);

    pool_kernel<<<M_TOTAL, 256>>>(x, ts);
    wsplit_kernel<<<(TOK_DIM * ENC_DIM) / 1024, 256>>>(W);
    dim3 gg(TOK_DIM / BN, M_TOTAL / BM);          // 16 x 32
    hgemm_kernel<<<gg, 256, HG_SMEM>>>(b);
    ln_kernel<<<M_TOTAL, 256>>>(gamma, beta, out);
}